// round 16
// baseline (speedup 1.0000x reference)
#include <cuda_runtime.h>

// ---------------- problem constants ----------------
#define BB    64
#define CC    3
#define NWIN  232
#define TT    8
#define CHUNK 29
#define DP    14
#define NN    42            // CC*DP
#define FF    256
#define H0    256
#define H1    128
#define NCLS  6
#define R1    (TT*BB*NN)    // 21504 rows of cur_in_all
#define R2    (BB*NN)       // 2688 rows per timestep
#define NBLK  148           // persistent-shaped grid (one wave, 1 blk/SM)

typedef unsigned long long ull;

// ---------------- scratch (device globals; no mallocs allowed) -------------
__device__ float g_cur[(size_t)R1 * H0];            // cur_in_all (fc_in output)
// class-plane layout: g_partial[cls][t][row]  (coalesced 42-float runs)
__device__ float g_partial[(size_t)NCLS * TT * R2];
__device__ float g_sums[TT * BB * NCLS];            // reduced per-(t,b,cls) sums

// ---------------- packed f32x2 helpers ----------------
__device__ __forceinline__ ull fma2(ull a, ull b, ull c) {
    asm("fma.rn.f32x2 %0, %1, %2, %0;" : "+l"(c) : "l"(a), "l"(b));
    return c;
}
__device__ __forceinline__ ull add2(ull a, ull b) {
    ull d;
    asm("add.rn.f32x2 %0, %1, %2;" : "=l"(d) : "l"(a), "l"(b));
    return d;
}
__device__ __forceinline__ ull dup2(float a) {
    unsigned u = __float_as_uint(a);
    ull d;
    asm("mov.b64 %0, {%1, %2};" : "=l"(d) : "r"(u), "r"(u));
    return d;
}

union F4U { float4 f; ull u[2]; float s[4]; };
union F2U { float2 f; ull u; float s[2]; };

__device__ __forceinline__ float clamp01(float v) {
    return fminf(fmaxf(v, 0.f), 1.f);
}

// ============================================================
// Kernel 1 (fused): cur_in_all = pool3d(x) @ W_in^T + b_in
// M=21504, N=256, K=256 fp32. BM=BN=128, BK=16; inner loop is the exact
// R8/R14 dup2 loop (bitwise-same accumulation). The A chunk is pooled
// directly from x during staging with the original pool's load set and
// add order (bitwise-same A values, proven rel_err=0 in R11).
// grid = (2 n-tiles, 168 m-tiles), n FASTEST: the two blocks reading the
// same x slice are co-resident -> x streams through L2 once.
// ============================================================
__global__ __launch_bounds__(256, 2) void gemm_fused_kernel(
    const float* __restrict__ x,
    const float* __restrict__ Win,
    const float* __restrict__ bin)
{
    __shared__ float As[16 * 132];
    __shared__ float Bs[16 * 132];

    int tid = threadIdx.x;
    int n0 = blockIdx.x * 128;      // n fastest -> twin co-residency
    int m0 = blockIdx.y * 128;
    int tx = tid & 15;
    int ty = tid >> 4;

    // ---- per-thread pooling geometry (8 rows, fixed across chunks) ----
    int jw    = tid & 15;           // wp == k-within-chunk
    int rbase = tid >> 4;           // row group 0..15
    int base32[8];                  // x row offset in units of 32 floats
    #pragma unroll
    for (int i = 0; i < 8; i++) {
        int row_g = m0 + rbase + 16 * i;
        int t   = row_g / (BB * NN);
        int rem = row_g % (BB * NN);
        int b   = rem / NN;
        int n   = rem % NN;
        int c   = n / DP;
        int d   = n % DP;
        base32[i] = ((b * CC + c) * NWIN + t * CHUNK + 2 * d) * 32;
    }
    const float2* x2 = (const float2*)x;

    // ---- per-thread B staging indices (2 float4 per chunk) ----
    int rB_[2], c4_[2];
    #pragma unroll
    for (int i = 0; i < 2; i++) {
        int idx = tid + i * 256;
        rB_[i] = idx >> 2;
        c4_[i] = (idx & 3) * 4;
    }

    ull acc[8][4];
    #pragma unroll
    for (int m = 0; m < 8; m++)
        #pragma unroll
        for (int nn = 0; nn < 4; nn++) acc[m][nn] = 0ull;

    for (int kc = 0; kc < 16; kc++) {
        if (kc > 0) __syncthreads();    // readers of previous chunk done

        // ---- stage B chunk (from Win; L2-resident after first wave) ----
        #pragma unroll
        for (int i = 0; i < 2; i++) {
            float4 vb = *(const float4*)(Win + (size_t)(n0 + rB_[i]) * H0
                                         + kc * 16 + c4_[i]);
            int r = rB_[i], c4 = c4_[i];
            Bs[(c4 + 0) * 132 + r] = vb.x;
            Bs[(c4 + 1) * 132 + r] = vb.y;
            Bs[(c4 + 2) * 132 + r] = vb.z;
            Bs[(c4 + 3) * 132 + r] = vb.w;
        }

        // ---- stage A chunk: pool 8 values directly from x ----
        // feature f = kc*16 + jw  ->  hp = kc, wp = jw; add order matches
        // the original pool kernel exactly.
        #pragma unroll
        for (int i = 0; i < 8; i++) {
            float2 v00 = x2[(base32[i] + 0 * 32 + 2 * kc + 0) * 16 + jw];
            float2 v01 = x2[(base32[i] + 0 * 32 + 2 * kc + 1) * 16 + jw];
            float2 v10 = x2[(base32[i] + 1 * 32 + 2 * kc + 0) * 16 + jw];
            float2 v11 = x2[(base32[i] + 1 * 32 + 2 * kc + 1) * 16 + jw];
            float s = 0.f;
            s += v00.x + v00.y;
            s += v01.x + v01.y;
            s += v10.x + v10.y;
            s += v11.x + v11.y;
            As[jw * 132 + rbase + 16 * i] = s * 0.125f;
        }
        __syncthreads();

        // ---- compute on this chunk (exact R8/R14 inner loop) ----
        #pragma unroll
        for (int kk = 0; kk < 16; kk++) {
            F4U a0, a1, b0, b1;
            a0.f = *(const float4*)&As[kk * 132 + ty * 8];
            a1.f = *(const float4*)&As[kk * 132 + ty * 8 + 4];
            b0.f = *(const float4*)&Bs[kk * 132 + tx * 8];
            b1.f = *(const float4*)&Bs[kk * 132 + tx * 8 + 4];
            ull bp[4] = { b0.u[0], b0.u[1], b1.u[0], b1.u[1] };
            float av[8] = { a0.s[0], a0.s[1], a0.s[2], a0.s[3],
                            a1.s[0], a1.s[1], a1.s[2], a1.s[3] };
            #pragma unroll
            for (int m = 0; m < 8; m++) {
                ull ad = dup2(av[m]);
                #pragma unroll
                for (int nn = 0; nn < 4; nn++)
                    acc[m][nn] = fma2(ad, bp[nn], acc[m][nn]);
            }
        }
    }

    F4U bi0, bi1;
    bi0.f = *(const float4*)(bin + n0 + tx * 8);
    bi1.f = *(const float4*)(bin + n0 + tx * 8 + 4);
    ull bp[4] = { bi0.u[0], bi0.u[1], bi1.u[0], bi1.u[1] };

    #pragma unroll
    for (int m = 0; m < 8; m++) {
        F4U o0, o1;
        o0.u[0] = add2(acc[m][0], bp[0]);
        o0.u[1] = add2(acc[m][1], bp[1]);
        o1.u[0] = add2(acc[m][2], bp[2]);
        o1.u[1] = add2(acc[m][3], bp[3]);
        float* outp = g_cur + (size_t)(m0 + ty * 8 + m) * H0 + n0 + tx * 8;
        *(float4*)outp = o0.f;
        *(float4*)(outp + 4) = o1.f;
    }
}

// ============================================================
// Kernel 2: ALL 8 timesteps fused in one persistent kernel (R14 version:
// batched phase-1 loads, software-pipelined phase-2 adds, class-plane
// partial writes).
// ============================================================
#define SROWS 20
#define WROW  130
#define SMEM_W_BYTES     (257 * WROW * 4)
#define SMEM_SPK2_OFF    SMEM_W_BYTES
#define SMEM_LST_OFF     (SMEM_SPK2_OFF + SROWS * H1 * 4)
#define SMEM_CNT_OFF     (SMEM_LST_OFF + SROWS * 256 * 2)
#define STEP_SMEM        (SMEM_CNT_OFF + SROWS * 4)

__global__ __launch_bounds__(256) void step_all_kernel(
    const float* __restrict__ W_hid, const float* __restrict__ b_hid,
    const float* __restrict__ beta_in, const float* __restrict__ thr_in,
    const float* __restrict__ beta_hid, const float* __restrict__ thr_hid,
    const float* __restrict__ W_out)
{
    extern __shared__ char smem[];
    float*          sW    = (float*)smem;
    float*          sSpk2 = (float*)(smem + SMEM_SPK2_OFF);
    unsigned short* sLst  = (unsigned short*)(smem + SMEM_LST_OFF);
    int*            sCnt  = (int*)(smem + SMEM_CNT_OFF);

    int tid  = threadIdx.x;
    int lane = tid & 31;
    int warp = tid >> 5;
    int r0 = (int)(((long long)blockIdx.x * R2) / NBLK);
    int r1 = (int)(((long long)(blockIdx.x + 1) * R2) / NBLK);

    // ---- stage W_hid transposed (k-major) + zero sentinel row, ONCE ----
    #pragma unroll 4
    for (int g = 0; g < H1; g++)
        sW[tid * WROW + g] = W_hid[g * H0 + tid];   // tid == k
    if (tid < H1) sW[256 * WROW + tid] = 0.f;

    // ---- hoisted LIF1 params + register-resident mem_in ----
    float thrA[8], betA[8];
    #pragma unroll
    for (int kb = 0; kb < 8; kb++) {
        int k = kb * 32 + lane;
        thrA[kb] = thr_in[k];
        betA[kb] = clamp01(beta_in[k]);
    }
    float memA[3][8];
    #pragma unroll
    for (int ri = 0; ri < 3; ri++)
        #pragma unroll
        for (int kb = 0; kb < 8; kb++) memA[ri][kb] = 0.f;

    // ---- hoisted LIF2 params + register-resident mem_hid ----
    int j = tid & 63;       // g-pair
    int q = tid >> 6;       // row-within-chunk
    const ull* sW2 = (const ull*)sW;
    F2U bh;  bh.f  = *(const float2*)(b_hid    + 2 * j);
    float2 bhf     = *(const float2*)(beta_hid + 2 * j);
    float betx = clamp01(bhf.x), bety = clamp01(bhf.y);
    float2 thh     = *(const float2*)(thr_hid  + 2 * j);
    float2 memh[5];
    #pragma unroll
    for (int c = 0; c < 5; c++) memh[c] = make_float2(0.f, 0.f);

    unsigned lmask = (1u << lane) - 1u;
    __syncthreads();

    for (int t = 0; t < TT; t++) {
        // ---- phase 1: LIF1 + warp-ballot compaction of active h per row ----
        #pragma unroll
        for (int ri = 0; ri < 3; ri++) {
            int rl = warp + ri * 8;
            if (rl < SROWS) {
                int row = r0 + rl;
                if (row < r1) {
                    unsigned short* lst = sLst + rl * 256;
                    const float* curp = g_cur + ((size_t)t * R2 + row) * H0;
                    float curv[8];
                    #pragma unroll
                    for (int kb = 0; kb < 8; kb++)
                        curv[kb] = curp[kb * 32 + lane];
                    unsigned bal[8];
                    int sv[8];
                    #pragma unroll
                    for (int kb = 0; kb < 8; kb++) {
                        float mem = memA[ri][kb];
                        float rst = (mem > thrA[kb]) ? thrA[kb] : 0.f;
                        mem = fmaf(betA[kb], mem, curv[kb]) - rst;
                        memA[ri][kb] = mem;
                        sv[kb] = (mem - thrA[kb] > 0.f) ? 1 : 0;
                        bal[kb] = __ballot_sync(0xffffffffu, sv[kb]);
                    }
                    int cnt = 0;
                    #pragma unroll
                    for (int kb = 0; kb < 8; kb++) {
                        if (sv[kb]) lst[cnt + __popc(bal[kb] & lmask)] =
                                        (unsigned short)(kb * 32 + lane);
                        cnt += __popc(bal[kb]);
                    }
                    int cnt4 = (cnt + 3) & ~3;
                    if (lane < cnt4 - cnt) lst[cnt + lane] = 256;  // zero-row pad
                    if (lane == 0) sCnt[rl] = cnt4;
                } else if (lane == 0) {
                    sCnt[rl] = 0;
                }
            }
        }
        __syncthreads();

        // ---- phase 2+3: hidden current (pipelined compacted adds) + LIF2 ----
        #pragma unroll
        for (int c = 0; c < 5; c++) {
            int rl = c * 4 + q;
            int cnt4 = sCnt[rl];
            const unsigned short* lst = sLst + rl * 256;
            ull acc0 = bh.u;
            ull acc1 = 0ull;
            if (cnt4 > 0) {
                ushort4 kk = *(const ushort4*)(lst);
                ull w0 = sW2[(int)kk.x * 65 + j];
                ull w1 = sW2[(int)kk.y * 65 + j];
                ull w2 = sW2[(int)kk.z * 65 + j];
                ull w3 = sW2[(int)kk.w * 65 + j];
                for (int i = 4; i < cnt4; i += 4) {
                    ushort4 kn = *(const ushort4*)(lst + i);
                    ull n0 = sW2[(int)kn.x * 65 + j];
                    ull n1 = sW2[(int)kn.y * 65 + j];
                    ull n2 = sW2[(int)kn.z * 65 + j];
                    ull n3 = sW2[(int)kn.w * 65 + j];
                    acc0 = add2(acc0, w0);
                    acc1 = add2(acc1, w1);
                    acc0 = add2(acc0, w2);
                    acc1 = add2(acc1, w3);
                    w0 = n0; w1 = n1; w2 = n2; w3 = n3;
                }
                acc0 = add2(acc0, w0);
                acc1 = add2(acc1, w1);
                acc0 = add2(acc0, w2);
                acc1 = add2(acc1, w3);
            }
            ull accs = add2(acc0, acc1);

            int row = r0 + rl;
            if (row < r1) {
                F2U a; a.u = accs;
                float2 mem = memh[c];
                float rx = (mem.x > thh.x) ? thh.x : 0.f;
                float ry = (mem.y > thh.y) ? thh.y : 0.f;
                mem.x = fmaf(betx, mem.x, a.s[0]) - rx;
                mem.y = fmaf(bety, mem.y, a.s[1]) - ry;
                memh[c] = mem;
                float2 sp;
                sp.x = (mem.x - thh.x > 0.f) ? 1.f : 0.f;
                sp.y = (mem.y - thh.y > 0.f) ? 1.f : 0.f;
                *(float2*)(sSpk2 + rl * H1 + 2 * j) = sp;
            }
        }
        __syncthreads();

        // ---- phase 4: per-row readout partials (fixed-order reduce) ----
        for (int rl = warp; rl < SROWS; rl += 8) {
            int row = r0 + rl;
            if (row >= r1) continue;
            int n = row % NN;
            const float* wo = W_out + n * H1;
            float sv[4];
            #pragma unroll
            for (int gi = 0; gi < 4; gi++) sv[gi] = sSpk2[rl * H1 + gi * 32 + lane];
            #pragma unroll
            for (int cls = 0; cls < NCLS; cls++) {
                float p = 0.f;
                #pragma unroll
                for (int gi = 0; gi < 4; gi++)
                    p = fmaf(wo[cls * (NN * H1) + gi * 32 + lane], sv[gi], p);
                #pragma unroll
                for (int off = 16; off; off >>= 1)
                    p += __shfl_down_sync(0xffffffffu, p, off);
                if (lane == 0)
                    g_partial[((size_t)cls * TT + t) * R2 + row] = p;
            }
        }
    }
}

// ============================================================
// Kernel 3a: per-(t,b,cls) partial reduction (coalesced class planes).
// ============================================================
__global__ __launch_bounds__(256) void out_reduce_kernel(const float* __restrict__ b_out)
{
    int g = blockIdx.x * 256 + threadIdx.x;     // 0..3071
    if (g >= TT * BB * NCLS) return;
    int t  = g / (BB * NCLS);
    int r  = g % (BB * NCLS);
    int b  = r / NCLS;
    int cls = r % NCLS;

    float s = b_out[cls];
    const float* pp = g_partial + ((size_t)cls * TT + t) * R2 + (size_t)b * NN;
    #pragma unroll
    for (int n = 0; n < NN; n++) s += pp[n];
    g_sums[t * (BB * NCLS) + r] = s;
}

// ============================================================
// Kernel 3b: 8-step output-LIF chain (trivial).
// ============================================================
__global__ __launch_bounds__(BB * NCLS) void out_chain_kernel(
    const float* __restrict__ beta_out, float* __restrict__ out)
{
    int tid = threadIdx.x;                 // 0..383
    int cls = tid % NCLS;
    float beta = clamp01(beta_out[cls]);

    float sums[TT];
    #pragma unroll
    for (int t = 0; t < TT; t++) sums[t] = g_sums[t * (BB * NCLS) + tid];

    float mem = 0.f;
    #pragma unroll
    for (int t = 0; t < TT; t++) {
        float rst = (mem > 1.f) ? 1.f : 0.f;
        mem = fmaf(beta, mem, sums[t]) - rst;
        out[t * (BB * NCLS) + tid] = (mem - 1.f > 0.f) ? 1.f : 0.f;
    }
}

// ============================================================
// launch: single stream, no stream/event APIs (graph-capture safe).
// ============================================================
extern "C" void kernel_launch(void* const* d_in, const int* in_sizes, int n_in,
                              void* d_out, int out_size) {
    (void)in_sizes; (void)n_in; (void)out_size;
    const float* x        = (const float*)d_in[0];
    const float* W_in     = (const float*)d_in[1];
    const float* b_in     = (const float*)d_in[2];
    const float* W_hid    = (const float*)d_in[3];
    const float* b_hid    = (const float*)d_in[4];
    const float* W_out    = (const float*)d_in[5];
    const float* b_out    = (const float*)d_in[6];
    const float* beta_in  = (const float*)d_in[7];
    const float* thr_in   = (const float*)d_in[8];
    const float* beta_hid = (const float*)d_in[9];
    const float* thr_hid  = (const float*)d_in[10];
    const float* beta_out = (const float*)d_in[11];
    float* out = (float*)d_out;

    cudaFuncSetAttribute(step_all_kernel,
                         cudaFuncAttributeMaxDynamicSharedMemorySize, STEP_SMEM);

    // n-tile FASTEST: twin blocks of an m-tile are co-resident -> L2 shares x
    gemm_fused_kernel<<<dim3(H0 / 128, R1 / 128), 256>>>(x, W_in, b_in);
    step_all_kernel<<<NBLK, 256, STEP_SMEM>>>(W_hid, b_hid, beta_in, thr_in,
                                              beta_hid, thr_hid, W_out);
    out_reduce_kernel<<<12, 256>>>(b_out);
    out_chain_kernel<<<1, BB * NCLS>>>(beta_out, out);
}

// round 17
// speedup vs baseline: 1.1134x; 1.1134x over previous
#include <cuda_runtime.h>

// ---------------- problem constants ----------------
#define BB    64
#define CC    3
#define NWIN  232
#define TT    8
#define CHUNK 29
#define DP    14
#define NN    42            // CC*DP
#define FF    256
#define H0    256
#define H1    128
#define NCLS  6
#define R1    (TT*BB*NN)    // 21504 rows of cur_in_all
#define R2    (BB*NN)       // 2688 rows per timestep
#define NBLK  148           // persistent-shaped grid (one wave, 1 blk/SM)

typedef unsigned long long ull;

// ---------------- scratch (device globals; no mallocs allowed) -------------
__device__ float g_pr[(size_t)R1 * FF];             // pooled activations
__device__ float g_cur[(size_t)R1 * H0];            // cur_in_all (fc_in output)
// class-plane layout: g_partial[cls][t][row]  (coalesced 42-float runs)
__device__ float g_partial[(size_t)NCLS * TT * R2];
__device__ float g_sums[TT * BB * NCLS];            // reduced per-(t,b,cls) sums

// ---------------- packed f32x2 helpers ----------------
__device__ __forceinline__ ull fma2(ull a, ull b, ull c) {
    asm("fma.rn.f32x2 %0, %1, %2, %0;" : "+l"(c) : "l"(a), "l"(b));
    return c;
}
__device__ __forceinline__ ull add2(ull a, ull b) {
    ull d;
    asm("add.rn.f32x2 %0, %1, %2;" : "=l"(d) : "l"(a), "l"(b));
    return d;
}
__device__ __forceinline__ ull dup2(float a) {
    unsigned u = __float_as_uint(a);
    ull d;
    asm("mov.b64 %0, {%1, %2};" : "=l"(d) : "r"(u), "r"(u));
    return d;
}

union F4U { float4 f; ull u[2]; float s[4]; };
union F2U { float2 f; ull u; float s[2]; };

__device__ __forceinline__ float clamp01(float v) {
    return fminf(fmaxf(v, 0.f), 1.f);
}

// ============================================================
// Kernel 1: avg-pool3d (2,2,2)/(2,2,2) VALID, fused reshape to (R1, 256)
// ============================================================
__global__ __launch_bounds__(256) void pool_kernel(const float* __restrict__ x) {
    int row = blockIdx.x;
    int f   = threadIdx.x;

    int t   = row / (BB * NN);
    int rem = row % (BB * NN);
    int b   = rem / NN;
    int n   = rem % NN;
    int c   = n / DP;
    int d   = n % DP;
    int hp  = f >> 4;
    int wp  = f & 15;

    const float2* x2 = (const float2*)x;
    long long base = ((long long)(b * CC + c) * NWIN + t * CHUNK + 2 * d) * 32;

    float s = 0.f;
    #pragma unroll
    for (int kd = 0; kd < 2; kd++) {
        #pragma unroll
        for (int kh = 0; kh < 2; kh++) {
            float2 v = x2[(base + (long long)kd * 32 + 2 * hp + kh) * 16 + wp];
            s += v.x + v.y;
        }
    }
    g_pr[(size_t)row * FF + f] = s * 0.125f;
}

// ============================================================
// Kernel 2: cur_in_all = pr @ W_in^T + b_in   (M=21504, N=256, K=256), fp32
// EXACT R8/R14 version: double-buffered static smem, dup2 inner loop, occ 2.
// ============================================================
__global__ __launch_bounds__(256, 2) void gemm1_kernel(const float* __restrict__ Win,
                                                       const float* __restrict__ bin) {
    __shared__ float As[2][16 * 132];
    __shared__ float Bs[2][16 * 132];

    int tid = threadIdx.x;
    int m0 = blockIdx.x * 128;
    int n0 = blockIdx.y * 128;
    int tx = tid & 15;
    int ty = tid >> 4;

    int r_[2], c4_[2];
    #pragma unroll
    for (int i = 0; i < 2; i++) {
        int idx = tid + i * 256;
        r_[i]  = idx >> 2;
        c4_[i] = (idx & 3) * 4;
    }

    ull acc[8][4];
    #pragma unroll
    for (int m = 0; m < 8; m++)
        #pragma unroll
        for (int nn = 0; nn < 4; nn++) acc[m][nn] = 0ull;

    float4 pa[2], pb[2];
    #pragma unroll
    for (int i = 0; i < 2; i++) {
        pa[i] = *(const float4*)(g_pr + (size_t)(m0 + r_[i]) * FF + c4_[i]);
        pb[i] = *(const float4*)(Win + (size_t)(n0 + r_[i]) * H0 + c4_[i]);
    }
    #pragma unroll
    for (int i = 0; i < 2; i++) {
        int r = r_[i], c4 = c4_[i];
        As[0][(c4 + 0) * 132 + r] = pa[i].x;
        As[0][(c4 + 1) * 132 + r] = pa[i].y;
        As[0][(c4 + 2) * 132 + r] = pa[i].z;
        As[0][(c4 + 3) * 132 + r] = pa[i].w;
        Bs[0][(c4 + 0) * 132 + r] = pb[i].x;
        Bs[0][(c4 + 1) * 132 + r] = pb[i].y;
        Bs[0][(c4 + 2) * 132 + r] = pb[i].z;
        Bs[0][(c4 + 3) * 132 + r] = pb[i].w;
    }
    __syncthreads();

    for (int kc = 0; kc < 16; kc++) {
        int buf = kc & 1;
        if (kc < 15) {
            int k0 = (kc + 1) * 16;
            #pragma unroll
            for (int i = 0; i < 2; i++) {
                pa[i] = *(const float4*)(g_pr + (size_t)(m0 + r_[i]) * FF + k0 + c4_[i]);
                pb[i] = *(const float4*)(Win + (size_t)(n0 + r_[i]) * H0 + k0 + c4_[i]);
            }
        }

        #pragma unroll
        for (int kk = 0; kk < 16; kk++) {
            F4U a0, a1, b0, b1;
            a0.f = *(const float4*)&As[buf][kk * 132 + ty * 8];
            a1.f = *(const float4*)&As[buf][kk * 132 + ty * 8 + 4];
            b0.f = *(const float4*)&Bs[buf][kk * 132 + tx * 8];
            b1.f = *(const float4*)&Bs[buf][kk * 132 + tx * 8 + 4];
            ull bp[4] = { b0.u[0], b0.u[1], b1.u[0], b1.u[1] };
            float av[8] = { a0.s[0], a0.s[1], a0.s[2], a0.s[3],
                            a1.s[0], a1.s[1], a1.s[2], a1.s[3] };
            #pragma unroll
            for (int m = 0; m < 8; m++) {
                ull ad = dup2(av[m]);
                #pragma unroll
                for (int nn = 0; nn < 4; nn++)
                    acc[m][nn] = fma2(ad, bp[nn], acc[m][nn]);
            }
        }

        if (kc < 15) {
            int nb = buf ^ 1;
            #pragma unroll
            for (int i = 0; i < 2; i++) {
                int r = r_[i], c4 = c4_[i];
                As[nb][(c4 + 0) * 132 + r] = pa[i].x;
                As[nb][(c4 + 1) * 132 + r] = pa[i].y;
                As[nb][(c4 + 2) * 132 + r] = pa[i].z;
                As[nb][(c4 + 3) * 132 + r] = pa[i].w;
                Bs[nb][(c4 + 0) * 132 + r] = pb[i].x;
                Bs[nb][(c4 + 1) * 132 + r] = pb[i].y;
                Bs[nb][(c4 + 2) * 132 + r] = pb[i].z;
                Bs[nb][(c4 + 3) * 132 + r] = pb[i].w;
            }
            __syncthreads();
        }
    }

    F4U bi0, bi1;
    bi0.f = *(const float4*)(bin + n0 + tx * 8);
    bi1.f = *(const float4*)(bin + n0 + tx * 8 + 4);
    ull bp[4] = { bi0.u[0], bi0.u[1], bi1.u[0], bi1.u[1] };

    #pragma unroll
    for (int m = 0; m < 8; m++) {
        F4U o0, o1;
        o0.u[0] = add2(acc[m][0], bp[0]);
        o0.u[1] = add2(acc[m][1], bp[1]);
        o1.u[0] = add2(acc[m][2], bp[2]);
        o1.u[1] = add2(acc[m][3], bp[3]);
        float* outp = g_cur + (size_t)(m0 + ty * 8 + m) * H0 + n0 + tx * 8;
        *(float4*)outp = o0.f;
        *(float4*)(outp + 4) = o1.f;
    }
}

// ============================================================
// Kernel 3: ALL 8 timesteps fused, now with 512 THREADS (4 warps/SMSP)
// for latency hiding. Work partitioning changes only thread->row
// assignment; every per-row arithmetic order is identical to R14
// -> bitwise-same results.
// ============================================================
#define SROWS 20
#define WROW  130
#define SMEM_W_BYTES     (257 * WROW * 4)
#define SMEM_SPK2_OFF    SMEM_W_BYTES
#define SMEM_LST_OFF     (SMEM_SPK2_OFF + SROWS * H1 * 4)
#define SMEM_CNT_OFF     (SMEM_LST_OFF + SROWS * 256 * 2)
#define STEP_SMEM        (SMEM_CNT_OFF + SROWS * 4)

__global__ __launch_bounds__(512) void step_all_kernel(
    const float* __restrict__ W_hid, const float* __restrict__ b_hid,
    const float* __restrict__ beta_in, const float* __restrict__ thr_in,
    const float* __restrict__ beta_hid, const float* __restrict__ thr_hid,
    const float* __restrict__ W_out)
{
    extern __shared__ char smem[];
    float*          sW    = (float*)smem;
    float*          sSpk2 = (float*)(smem + SMEM_SPK2_OFF);
    unsigned short* sLst  = (unsigned short*)(smem + SMEM_LST_OFF);
    int*            sCnt  = (int*)(smem + SMEM_CNT_OFF);

    int tid  = threadIdx.x;
    int lane = tid & 31;
    int warp = tid >> 5;               // 0..15
    int r0 = (int)(((long long)blockIdx.x * R2) / NBLK);
    int r1 = (int)(((long long)(blockIdx.x + 1) * R2) / NBLK);

    // ---- stage W_hid transposed (k-major) + zero sentinel row, ONCE ----
    {
        int ks = tid & 255;            // k index
        int gh = (tid >> 8) * 64;      // each thread stages 64 g values
        #pragma unroll 4
        for (int g = gh; g < gh + 64; g++)
            sW[ks * WROW + g] = W_hid[g * H0 + ks];
        if (tid < H1) sW[256 * WROW + tid] = 0.f;
    }

    // ---- hoisted LIF1 params + register-resident mem_in ----
    float thrA[8], betA[8];
    #pragma unroll
    for (int kb = 0; kb < 8; kb++) {
        int k = kb * 32 + lane;
        thrA[kb] = thr_in[k];
        betA[kb] = clamp01(beta_in[k]);
    }
    float memA[2][8];                  // rl = warp + ri*16, ri<2
    #pragma unroll
    for (int ri = 0; ri < 2; ri++)
        #pragma unroll
        for (int kb = 0; kb < 8; kb++) memA[ri][kb] = 0.f;

    // ---- hoisted LIF2 params + register-resident mem_hid ----
    int j = tid & 63;                  // g-pair
    int q = tid >> 6;                  // 0..7 row-groups
    const ull* sW2 = (const ull*)sW;
    F2U bh;  bh.f  = *(const float2*)(b_hid    + 2 * j);
    float2 bhf     = *(const float2*)(beta_hid + 2 * j);
    float betx = clamp01(bhf.x), bety = clamp01(bhf.y);
    float2 thh     = *(const float2*)(thr_hid  + 2 * j);
    float2 memh[3];                    // rl = c*8 + q, c<3
    #pragma unroll
    for (int c = 0; c < 3; c++) memh[c] = make_float2(0.f, 0.f);

    unsigned lmask = (1u << lane) - 1u;
    __syncthreads();

    for (int t = 0; t < TT; t++) {
        // ---- phase 1: LIF1 + warp-ballot compaction of active h per row ----
        #pragma unroll
        for (int ri = 0; ri < 2; ri++) {
            int rl = warp + ri * 16;
            if (rl < SROWS) {
                int row = r0 + rl;
                if (row < r1) {
                    unsigned short* lst = sLst + rl * 256;
                    const float* curp = g_cur + ((size_t)t * R2 + row) * H0;
                    float curv[8];
                    #pragma unroll
                    for (int kb = 0; kb < 8; kb++)
                        curv[kb] = curp[kb * 32 + lane];
                    unsigned bal[8];
                    int sv[8];
                    #pragma unroll
                    for (int kb = 0; kb < 8; kb++) {
                        float mem = memA[ri][kb];
                        float rst = (mem > thrA[kb]) ? thrA[kb] : 0.f;
                        mem = fmaf(betA[kb], mem, curv[kb]) - rst;
                        memA[ri][kb] = mem;
                        sv[kb] = (mem - thrA[kb] > 0.f) ? 1 : 0;
                        bal[kb] = __ballot_sync(0xffffffffu, sv[kb]);
                    }
                    int cnt = 0;
                    #pragma unroll
                    for (int kb = 0; kb < 8; kb++) {
                        if (sv[kb]) lst[cnt + __popc(bal[kb] & lmask)] =
                                        (unsigned short)(kb * 32 + lane);
                        cnt += __popc(bal[kb]);
                    }
                    int cnt4 = (cnt + 3) & ~3;
                    if (lane < cnt4 - cnt) lst[cnt + lane] = 256;  // zero-row pad
                    if (lane == 0) sCnt[rl] = cnt4;
                } else if (lane == 0) {
                    sCnt[rl] = 0;
                }
            }
        }
        __syncthreads();

        // ---- phase 2+3: hidden current (pipelined compacted adds) + LIF2 ----
        #pragma unroll
        for (int c = 0; c < 3; c++) {
            int rl = c * 8 + q;
            if (rl >= SROWS) break;
            int cnt4 = sCnt[rl];
            const unsigned short* lst = sLst + rl * 256;
            ull acc0 = bh.u;
            ull acc1 = 0ull;
            if (cnt4 > 0) {
                ushort4 kk = *(const ushort4*)(lst);
                ull w0 = sW2[(int)kk.x * 65 + j];
                ull w1 = sW2[(int)kk.y * 65 + j];
                ull w2 = sW2[(int)kk.z * 65 + j];
                ull w3 = sW2[(int)kk.w * 65 + j];
                for (int i = 4; i < cnt4; i += 4) {
                    ushort4 kn = *(const ushort4*)(lst + i);
                    ull n0 = sW2[(int)kn.x * 65 + j];
                    ull n1 = sW2[(int)kn.y * 65 + j];
                    ull n2 = sW2[(int)kn.z * 65 + j];
                    ull n3 = sW2[(int)kn.w * 65 + j];
                    acc0 = add2(acc0, w0);
                    acc1 = add2(acc1, w1);
                    acc0 = add2(acc0, w2);
                    acc1 = add2(acc1, w3);
                    w0 = n0; w1 = n1; w2 = n2; w3 = n3;
                }
                acc0 = add2(acc0, w0);
                acc1 = add2(acc1, w1);
                acc0 = add2(acc0, w2);
                acc1 = add2(acc1, w3);
            }
            ull accs = add2(acc0, acc1);

            int row = r0 + rl;
            if (row < r1) {
                F2U a; a.u = accs;
                float2 mem = memh[c];
                float rx = (mem.x > thh.x) ? thh.x : 0.f;
                float ry = (mem.y > thh.y) ? thh.y : 0.f;
                mem.x = fmaf(betx, mem.x, a.s[0]) - rx;
                mem.y = fmaf(bety, mem.y, a.s[1]) - ry;
                memh[c] = mem;
                float2 sp;
                sp.x = (mem.x - thh.x > 0.f) ? 1.f : 0.f;
                sp.y = (mem.y - thh.y > 0.f) ? 1.f : 0.f;
                *(float2*)(sSpk2 + rl * H1 + 2 * j) = sp;
            }
        }
        __syncthreads();

        // ---- phase 4: per-row readout partials (fixed-order reduce) ----
        for (int rl = warp; rl < SROWS; rl += 16) {
            int row = r0 + rl;
            if (row >= r1) continue;
            int n = row % NN;
            const float* wo = W_out + n * H1;
            float sv[4];
            #pragma unroll
            for (int gi = 0; gi < 4; gi++) sv[gi] = sSpk2[rl * H1 + gi * 32 + lane];
            #pragma unroll
            for (int cls = 0; cls < NCLS; cls++) {
                float p = 0.f;
                #pragma unroll
                for (int gi = 0; gi < 4; gi++)
                    p = fmaf(wo[cls * (NN * H1) + gi * 32 + lane], sv[gi], p);
                #pragma unroll
                for (int off = 16; off; off >>= 1)
                    p += __shfl_down_sync(0xffffffffu, p, off);
                if (lane == 0)
                    g_partial[((size_t)cls * TT + t) * R2 + row] = p;
            }
        }
    }
}

// ============================================================
// Kernel 4a: per-(t,b,cls) partial reduction (coalesced class planes).
// ============================================================
__global__ __launch_bounds__(256) void out_reduce_kernel(const float* __restrict__ b_out)
{
    int g = blockIdx.x * 256 + threadIdx.x;     // 0..3071
    if (g >= TT * BB * NCLS) return;
    int t  = g / (BB * NCLS);
    int r  = g % (BB * NCLS);
    int b  = r / NCLS;
    int cls = r % NCLS;

    float s = b_out[cls];
    const float* pp = g_partial + ((size_t)cls * TT + t) * R2 + (size_t)b * NN;
    #pragma unroll
    for (int n = 0; n < NN; n++) s += pp[n];
    g_sums[t * (BB * NCLS) + r] = s;
}

// ============================================================
// Kernel 4b: 8-step output-LIF chain (trivial).
// ============================================================
__global__ __launch_bounds__(BB * NCLS) void out_chain_kernel(
    const float* __restrict__ beta_out, float* __restrict__ out)
{
    int tid = threadIdx.x;                 // 0..383
    int cls = tid % NCLS;
    float beta = clamp01(beta_out[cls]);

    float sums[TT];
    #pragma unroll
    for (int t = 0; t < TT; t++) sums[t] = g_sums[t * (BB * NCLS) + tid];

    float mem = 0.f;
    #pragma unroll
    for (int t = 0; t < TT; t++) {
        float rst = (mem > 1.f) ? 1.f : 0.f;
        mem = fmaf(beta, mem, sums[t]) - rst;
        out[t * (BB * NCLS) + tid] = (mem - 1.f > 0.f) ? 1.f : 0.f;
    }
}

// ============================================================
// launch: single stream, no stream/event APIs (graph-capture safe).
// ============================================================
extern "C" void kernel_launch(void* const* d_in, const int* in_sizes, int n_in,
                              void* d_out, int out_size) {
    (void)in_sizes; (void)n_in; (void)out_size;
    const float* x        = (const float*)d_in[0];
    const float* W_in     = (const float*)d_in[1];
    const float* b_in     = (const float*)d_in[2];
    const float* W_hid    = (const float*)d_in[3];
    const float* b_hid    = (const float*)d_in[4];
    const float* W_out    = (const float*)d_in[5];
    const float* b_out    = (const float*)d_in[6];
    const float* beta_in  = (const float*)d_in[7];
    const float* thr_in   = (const float*)d_in[8];
    const float* beta_hid = (const float*)d_in[9];
    const float* thr_hid  = (const float*)d_in[10];
    const float* beta_out = (const float*)d_in[11];
    float* out = (float*)d_out;

    cudaFuncSetAttribute(step_all_kernel,
                         cudaFuncAttributeMaxDynamicSharedMemorySize, STEP_SMEM);

    pool_kernel<<<R1, 256>>>(x);
    gemm1_kernel<<<dim3(R1 / 128, H0 / 128), 256>>>(W_in, b_in);
    step_all_kernel<<<NBLK, 512, STEP_SMEM>>>(W_hid, b_hid, beta_in, thr_in,
                                              beta_hid, thr_hid, W_out);
    out_reduce_kernel<<<12, 256>>>(b_out);
    out_chain_kernel<<<1, BB * NCLS>>>(beta_out, out);
}